// round 3
// baseline (speedup 1.0000x reference)
#include <cuda_runtime.h>
#include <cuda_bf16.h>

// BoundaryLoss: mean(sigmoid(logits) * EDT2D(target)), [8,1,256,256].
//
// k_rowdist:  warp-per-row exact 1D distance^2 (shuffle scans, no barriers).
// k_edt_loss: per-(image, 16-col strip) CTA; dr2 strip staged in smem; exact
//             column min via per-thread expanding-radius early-exit search;
//             fused sigmoid + reduction.

#define B 8
#define H 256
#define W 256
#define NPIX (B * H * W)          // 524288
#define BIGD 1000000.0f
#define TW 16                     // column-strip width for stage 2
#define FULL 0xffffffffu

__device__ float g_dr2[NPIX];     // scratch: squared 1D row distances

__global__ void k_rowdist(const int* __restrict__ target,
                          float* __restrict__ out)
{
    if (blockIdx.x == 0 && threadIdx.x == 0) *out = 0.0f;

    const int lane = threadIdx.x & 31;
    const int warp = threadIdx.x >> 5;
    const int row  = (blockIdx.x << 3) + warp;     // 8 rows per block
    const int base = row * W;
    const int w0   = lane << 3;                    // 8 pixels per lane

    // vectorized load of this lane's 8 target values
    const int4* tp = reinterpret_cast<const int4*>(target + base + w0);
    const int4 t0 = tp[0];
    const int4 t1 = tp[1];
    int fg[8];
    fg[0] = t0.x > 0; fg[1] = t0.y > 0; fg[2] = t0.z > 0; fg[3] = t0.w > 0;
    fg[4] = t1.x > 0; fg[5] = t1.y > 0; fg[6] = t1.z > 0; fg[7] = t1.w > 0;

    // ---- left pass: nearest fg index <= w  (prefix max of (fg? w : -1))
    int pl[8];
    int run = -1;
#pragma unroll
    for (int k = 0; k < 8; ++k) {
        const int cand = fg[k] ? (w0 + k) : -1;
        run = max(run, cand);
        pl[k] = run;
    }
    int x = run;                                   // lane-inclusive value
#pragma unroll
    for (int off = 1; off < 32; off <<= 1) {
        const int y = __shfl_up_sync(FULL, x, off);
        if (lane >= off) x = max(x, y);
    }
    int exl = __shfl_up_sync(FULL, x, 1);          // exclusive prefix (lanes)
    if (lane == 0) exl = -1;

    // ---- right pass: nearest fg index >= w  (suffix min of (fg? w : 512))
    int pr[8];
    int run2 = 512;
#pragma unroll
    for (int k = 7; k >= 0; --k) {
        const int cand = fg[k] ? (w0 + k) : 512;
        run2 = min(run2, cand);
        pr[k] = run2;
    }
    int x2 = run2;
#pragma unroll
    for (int off = 1; off < 32; off <<= 1) {
        const int y = __shfl_down_sync(FULL, x2, off);
        if (lane + off < 32) x2 = min(x2, y);
    }
    int exr = __shfl_down_sync(FULL, x2, 1);       // exclusive suffix (lanes)
    if (lane == 31) exr = 512;

    // ---- combine, square, store (vectorized)
    float o[8];
#pragma unroll
    for (int k = 0; k < 8; ++k) {
        const int L = max(pl[k], exl);
        const int R = min(pr[k], exr);
        const float dl = (L >= 0)  ? (float)(w0 + k - L) : BIGD;
        const float dr = (R < 512) ? (float)(R - (w0 + k)) : BIGD;
        const float d  = fminf(dl, dr);
        o[k] = d * d;
    }
    float4* op = reinterpret_cast<float4*>(g_dr2 + base + w0);
    op[0] = make_float4(o[0], o[1], o[2], o[3]);
    op[1] = make_float4(o[4], o[5], o[6], o[7]);
}

__global__ void k_edt_loss(const float* __restrict__ logits,
                           float* __restrict__ out)
{
    __shared__ float s[H * TW];                    // 16 KB column strip

    const int b  = blockIdx.x >> 4;                // image
    const int c0 = (blockIdx.x & 15) * TW;         // strip start column
    const int t  = threadIdx.x;

    const float* src = g_dr2 + b * H * W + c0;
    const float* lg  = logits + b * H * W + c0;

    // stage strip into smem: 256 rows x 16 cols = 1024 float4
#pragma unroll
    for (int n = t; n < (H * TW) / 4; n += 256) {
        const int row = n >> 2;
        const int q   = n & 3;
        const float4 v = *reinterpret_cast<const float4*>(src + row * W + q * 4);
        *reinterpret_cast<float4*>(s + row * TW + q * 4) = v;
    }
    __syncthreads();

    const int c  = t & (TW - 1);                   // column within strip
    const int i0 = t >> 4;                         // base row (0..15)

    float acc = 0.0f;
#pragma unroll
    for (int k = 0; k < 16; ++k) {
        const int i = i0 + (k << 4);
        float cur = s[i * TW + c];
        // exact column min: min_j dr2[j] + (i-j)^2; stop once r^2 >= cur
        for (int r = 1; (float)(r * r) < cur; ++r) {
            const float rr = (float)(r * r);
            if (i >= r)     cur = fminf(cur, s[(i - r) * TW + c] + rr);
            if (i + r < H)  cur = fminf(cur, s[(i + r) * TW + c] + rr);
        }
        const float xv   = lg[i * W + c];
        const float prob = 1.0f / (1.0f + __expf(-xv));
        acc += prob * sqrtf(cur);
    }
    acc *= (1.0f / (float)NPIX);

    // block reduction -> single atomic per CTA
#pragma unroll
    for (int o = 16; o; o >>= 1)
        acc += __shfl_xor_sync(FULL, acc, o);

    __shared__ float ws[8];
    if ((t & 31) == 0) ws[t >> 5] = acc;
    __syncthreads();
    if (t == 0) {
        float v = ws[0];
#pragma unroll
        for (int k = 1; k < 8; ++k) v += ws[k];
        atomicAdd(out, v);
    }
}

extern "C" void kernel_launch(void* const* d_in, const int* in_sizes, int n_in,
                              void* d_out, int out_size)
{
    const float* logits = (const float*)d_in[0];
    const int*   target = (const int*)d_in[1];
    float*       out    = (float*)d_out;

    k_rowdist<<<(B * H) / 8, 256>>>(target, out);
    k_edt_loss<<<B * (W / TW), 256>>>(logits, out);
}

// round 5
// speedup vs baseline: 1.4090x; 1.4090x over previous
#include <cuda_runtime.h>
#include <cuda_bf16.h>

// BoundaryLoss: mean(sigmoid(logits) * EDT2D(target)), [8,1,256,256].
//
// k_rowdist:  warp-per-row exact 1D distance^2 (shuffle scans, no barriers).
// k_edt_loss: 1 thread / pixel (grid 2048). Exact column min
//             D2(i,w) = min_j dr2[j,w] + (i-j)^2 computed as:
//               batch: 9 independent loads covering j in [i-4, i+4] (MLP),
//               tail:  rare dependent expand loop for r >= 5 (cur > 25).
//             Fused sigmoid + block reduction + one atomicAdd per CTA.

#define B 8
#define H 256
#define W 256
#define NPIX (B * H * W)          // 524288
#define BIGD 1000000.0f
#define FULL 0xffffffffu

__device__ float g_dr2[NPIX];     // scratch: squared 1D row distances

__global__ void k_rowdist(const int* __restrict__ target,
                          float* __restrict__ out)
{
    if (blockIdx.x == 0 && threadIdx.x == 0) *out = 0.0f;

    const int lane = threadIdx.x & 31;
    const int warp = threadIdx.x >> 5;
    const int row  = (blockIdx.x << 3) + warp;     // 8 rows per block
    const int base = row * W;
    const int w0   = lane << 3;                    // 8 pixels per lane

    const int4* tp = reinterpret_cast<const int4*>(target + base + w0);
    const int4 t0 = tp[0];
    const int4 t1 = tp[1];
    int fg[8];
    fg[0] = t0.x > 0; fg[1] = t0.y > 0; fg[2] = t0.z > 0; fg[3] = t0.w > 0;
    fg[4] = t1.x > 0; fg[5] = t1.y > 0; fg[6] = t1.z > 0; fg[7] = t1.w > 0;

    // left pass: nearest fg index <= w (prefix max of (fg? w : -1))
    int pl[8];
    int run = -1;
#pragma unroll
    for (int k = 0; k < 8; ++k) {
        const int cand = fg[k] ? (w0 + k) : -1;
        run = max(run, cand);
        pl[k] = run;
    }
    int x = run;
#pragma unroll
    for (int off = 1; off < 32; off <<= 1) {
        const int y = __shfl_up_sync(FULL, x, off);
        if (lane >= off) x = max(x, y);
    }
    int exl = __shfl_up_sync(FULL, x, 1);
    if (lane == 0) exl = -1;

    // right pass: nearest fg index >= w (suffix min of (fg? w : 512))
    int pr[8];
    int run2 = 512;
#pragma unroll
    for (int k = 7; k >= 0; --k) {
        const int cand = fg[k] ? (w0 + k) : 512;
        run2 = min(run2, cand);
        pr[k] = run2;
    }
    int x2 = run2;
#pragma unroll
    for (int off = 1; off < 32; off <<= 1) {
        const int y = __shfl_down_sync(FULL, x2, off);
        if (lane + off < 32) x2 = min(x2, y);
    }
    int exr = __shfl_down_sync(FULL, x2, 1);
    if (lane == 31) exr = 512;

    float o[8];
#pragma unroll
    for (int k = 0; k < 8; ++k) {
        const int L = max(pl[k], exl);
        const int R = min(pr[k], exr);
        const float dl = (L >= 0)  ? (float)(w0 + k - L) : BIGD;
        const float dr = (R < 512) ? (float)(R - (w0 + k)) : BIGD;
        const float d  = fminf(dl, dr);
        o[k] = d * d;
    }
    float4* op = reinterpret_cast<float4*>(g_dr2 + base + w0);
    op[0] = make_float4(o[0], o[1], o[2], o[3]);
    op[1] = make_float4(o[4], o[5], o[6], o[7]);
}

__global__ void k_edt_loss(const float* __restrict__ logits,
                           float* __restrict__ out)
{
    const int idx = blockIdx.x * blockDim.x + threadIdx.x;   // 0..NPIX-1
    const int i   = (idx >> 8) & (H - 1);                    // row within image

    // ---- batch phase: 10 independent loads (center, +-1..4, logits) ----
    const float xv = logits[idx];

    const float c0 = g_dr2[idx];
    float u1 = (i >= 1)    ? g_dr2[idx - (1 << 8)] : BIGD;
    float d1 = (i + 1 < H) ? g_dr2[idx + (1 << 8)] : BIGD;
    float u2 = (i >= 2)    ? g_dr2[idx - (2 << 8)] : BIGD;
    float d2 = (i + 2 < H) ? g_dr2[idx + (2 << 8)] : BIGD;
    float u3 = (i >= 3)    ? g_dr2[idx - (3 << 8)] : BIGD;
    float d3 = (i + 3 < H) ? g_dr2[idx + (3 << 8)] : BIGD;
    float u4 = (i >= 4)    ? g_dr2[idx - (4 << 8)] : BIGD;
    float d4 = (i + 4 < H) ? g_dr2[idx + (4 << 8)] : BIGD;

    float cur = c0;
    cur = fminf(cur, fminf(u1, d1) + 1.0f);
    cur = fminf(cur, fminf(u2, d2) + 4.0f);
    cur = fminf(cur, fminf(u3, d3) + 9.0f);
    cur = fminf(cur, fminf(u4, d4) + 16.0f);

    // ---- rare tail: expand r >= 5 only while r^2 < cur ----
    if (cur > 25.0f) {
        for (int r = 5; r < H && (float)(r * r) < cur; ++r) {
            const float rr = (float)(r * r);
            if (i >= r)    cur = fminf(cur, g_dr2[idx - (r << 8)] + rr);
            if (i + r < H) cur = fminf(cur, g_dr2[idx + (r << 8)] + rr);
        }
    }

    const float prob = 1.0f / (1.0f + __expf(-xv));
    float val = prob * sqrtf(cur) * (1.0f / (float)NPIX);

    // block reduction -> one atomic per CTA
#pragma unroll
    for (int o = 16; o; o >>= 1)
        val += __shfl_xor_sync(FULL, val, o);

    __shared__ float ws[8];
    if ((threadIdx.x & 31) == 0) ws[threadIdx.x >> 5] = val;
    __syncthreads();
    if (threadIdx.x == 0) {
        float v = ws[0];
#pragma unroll
        for (int k = 1; k < 8; ++k) v += ws[k];
        atomicAdd(out, v);
    }
}

extern "C" void kernel_launch(void* const* d_in, const int* in_sizes, int n_in,
                              void* d_out, int out_size)
{
    const float* logits = (const float*)d_in[0];
    const int*   target = (const int*)d_in[1];
    float*       out    = (float*)d_out;

    k_rowdist<<<(B * H) / 8, 256>>>(target, out);
    k_edt_loss<<<NPIX / 256, 256>>>(logits, out);
}

// round 6
// speedup vs baseline: 1.7481x; 1.2407x over previous
#include <cuda_runtime.h>
#include <cuda_bf16.h>

// BoundaryLoss: mean(sigmoid(logits) * EDT2D(target)), [8,1,256,256].
//
// k_rowdist:  warp-per-row exact 1D distance^2 (shuffle scans, no barriers).
// k_edt_loss: 1 thread = 4 consecutive pixels (float4). Exact column min
//             D2(i,w) = min_j dr2[j,w] + (i-j)^2:
//               batch: 9 vector loads covering j in [i-4, i+4] (MLP, LDG.128),
//               tail:  rare scalar expand loop for r >= 5 (cur > 25).
//             Fused sigmoid + block reduction + one atomicAdd per CTA.

#define B 8
#define H 256
#define W 256
#define NPIX (B * H * W)          // 524288
#define BIGD 1000000.0f
#define FULL 0xffffffffu
#define RW4 (W / 4)               // 64 float4 per row

__device__ float g_dr2[NPIX];     // scratch: squared 1D row distances

__global__ void k_rowdist(const int* __restrict__ target,
                          float* __restrict__ out)
{
    if (blockIdx.x == 0 && threadIdx.x == 0) *out = 0.0f;

    const int lane = threadIdx.x & 31;
    const int warp = threadIdx.x >> 5;
    const int row  = (blockIdx.x << 3) + warp;     // 8 rows per block
    const int base = row * W;
    const int w0   = lane << 3;                    // 8 pixels per lane

    const int4* tp = reinterpret_cast<const int4*>(target + base + w0);
    const int4 t0 = tp[0];
    const int4 t1 = tp[1];
    int fg[8];
    fg[0] = t0.x > 0; fg[1] = t0.y > 0; fg[2] = t0.z > 0; fg[3] = t0.w > 0;
    fg[4] = t1.x > 0; fg[5] = t1.y > 0; fg[6] = t1.z > 0; fg[7] = t1.w > 0;

    // left pass: nearest fg index <= w (prefix max of (fg? w : -1))
    int pl[8];
    int run = -1;
#pragma unroll
    for (int k = 0; k < 8; ++k) {
        const int cand = fg[k] ? (w0 + k) : -1;
        run = max(run, cand);
        pl[k] = run;
    }
    int x = run;
#pragma unroll
    for (int off = 1; off < 32; off <<= 1) {
        const int y = __shfl_up_sync(FULL, x, off);
        if (lane >= off) x = max(x, y);
    }
    int exl = __shfl_up_sync(FULL, x, 1);
    if (lane == 0) exl = -1;

    // right pass: nearest fg index >= w (suffix min of (fg? w : 512))
    int pr[8];
    int run2 = 512;
#pragma unroll
    for (int k = 7; k >= 0; --k) {
        const int cand = fg[k] ? (w0 + k) : 512;
        run2 = min(run2, cand);
        pr[k] = run2;
    }
    int x2 = run2;
#pragma unroll
    for (int off = 1; off < 32; off <<= 1) {
        const int y = __shfl_down_sync(FULL, x2, off);
        if (lane + off < 32) x2 = min(x2, y);
    }
    int exr = __shfl_down_sync(FULL, x2, 1);
    if (lane == 31) exr = 512;

    float o[8];
#pragma unroll
    for (int k = 0; k < 8; ++k) {
        const int L = max(pl[k], exl);
        const int R = min(pr[k], exr);
        const float dl = (L >= 0)  ? (float)(w0 + k - L) : BIGD;
        const float dr = (R < 512) ? (float)(R - (w0 + k)) : BIGD;
        const float d  = fminf(dl, dr);
        o[k] = d * d;
    }
    float4* op = reinterpret_cast<float4*>(g_dr2 + base + w0);
    op[0] = make_float4(o[0], o[1], o[2], o[3]);
    op[1] = make_float4(o[4], o[5], o[6], o[7]);
}

__device__ __forceinline__ float4 fmin4a(float4 a, float4 bu, float4 bd, float rr)
{
    a.x = fminf(a.x, fminf(bu.x, bd.x) + rr);
    a.y = fminf(a.y, fminf(bu.y, bd.y) + rr);
    a.z = fminf(a.z, fminf(bu.z, bd.z) + rr);
    a.w = fminf(a.w, fminf(bu.w, bd.w) + rr);
    return a;
}

__global__ void k_edt_loss(const float* __restrict__ logits,
                           float* __restrict__ out)
{
    const int v  = blockIdx.x * blockDim.x + threadIdx.x;  // float4 index
    const int i  = (v / RW4) & (H - 1);                    // row within image

    const float4* dr = reinterpret_cast<const float4*>(g_dr2);
    const float4  xv = reinterpret_cast<const float4*>(logits)[v];

    const float4 big = make_float4(BIGD, BIGD, BIGD, BIGD);

    // batch phase: 9 independent vector loads covering j in [i-4, i+4]
    float4 cur = dr[v];
    const float4 u1 = (i >= 1)    ? dr[v - 1 * RW4] : big;
    const float4 d1 = (i + 1 < H) ? dr[v + 1 * RW4] : big;
    const float4 u2 = (i >= 2)    ? dr[v - 2 * RW4] : big;
    const float4 d2 = (i + 2 < H) ? dr[v + 2 * RW4] : big;
    const float4 u3 = (i >= 3)    ? dr[v - 3 * RW4] : big;
    const float4 d3 = (i + 3 < H) ? dr[v + 3 * RW4] : big;
    const float4 u4 = (i >= 4)    ? dr[v - 4 * RW4] : big;
    const float4 d4 = (i + 4 < H) ? dr[v + 4 * RW4] : big;

    cur = fmin4a(cur, u1, d1, 1.0f);
    cur = fmin4a(cur, u2, d2, 4.0f);
    cur = fmin4a(cur, u3, d3, 9.0f);
    cur = fmin4a(cur, u4, d4, 16.0f);

    // rare exact tail: r >= 5, scalar per component
    if (fmaxf(fmaxf(cur.x, cur.y), fmaxf(cur.z, cur.w)) > 25.0f) {
        float* c = &cur.x;
        const int p0 = v << 2;                     // scalar pixel base
#pragma unroll
        for (int q = 0; q < 4; ++q) {
            for (int r = 5; r < H && (float)(r * r) < c[q]; ++r) {
                const float rr = (float)(r * r);
                if (i >= r)    c[q] = fminf(c[q], g_dr2[p0 + q - (r << 8)] + rr);
                if (i + r < H) c[q] = fminf(c[q], g_dr2[p0 + q + (r << 8)] + rr);
            }
        }
    }

    const float px = 1.0f / (1.0f + __expf(-xv.x));
    const float py = 1.0f / (1.0f + __expf(-xv.y));
    const float pz = 1.0f / (1.0f + __expf(-xv.z));
    const float pw = 1.0f / (1.0f + __expf(-xv.w));

    float val = px * sqrtf(cur.x) + py * sqrtf(cur.y)
              + pz * sqrtf(cur.z) + pw * sqrtf(cur.w);
    val *= (1.0f / (float)NPIX);

    // block reduction -> one atomic per CTA
#pragma unroll
    for (int o = 16; o; o >>= 1)
        val += __shfl_xor_sync(FULL, val, o);

    __shared__ float ws[8];
    if ((threadIdx.x & 31) == 0) ws[threadIdx.x >> 5] = val;
    __syncthreads();
    if (threadIdx.x == 0) {
        float t = ws[0];
#pragma unroll
        for (int k = 1; k < 8; ++k) t += ws[k];
        atomicAdd(out, t);
    }
}

extern "C" void kernel_launch(void* const* d_in, const int* in_sizes, int n_in,
                              void* d_out, int out_size)
{
    const float* logits = (const float*)d_in[0];
    const int*   target = (const int*)d_in[1];
    float*       out    = (float*)d_out;

    k_rowdist<<<(B * H) / 8, 256>>>(target, out);
    k_edt_loss<<<(NPIX / 4) / 256, 256>>>(logits, out);
}